// round 1
// baseline (speedup 1.0000x reference)
#include <cuda_runtime.h>
#include <cuda_bf16.h>

// ---------------------------------------------------------------------------
// SCC3D window attention block, round 0: correct fp32 baseline.
//   x(192,256,256) -> qkv GEMM -> per-(b,h) attention w/ bias+mask+softmax
//   -> proj GEMM -> out(192,256,256)
// ---------------------------------------------------------------------------

#define B_TOT   192
#define NTOK    256
#define CDIM    256
#define HEADS   8
#define HDIM    32
#define NWIN    64

// Scratch (device globals: allocation-free)
__device__ float g_qkv[B_TOT * NTOK * 3 * CDIM];       // (B_, N, 3C) = 151 MB
__device__ float g_attn_out[B_TOT * NTOK * CDIM];      // (B_, N, C)  =  50 MB
__device__ float g_bias[HEADS * NTOK * NTOK];          // (H, N, N)   =   2 MB

// ---------------------------------------------------------------------------
// Bias gather: bias[h][n][m] = table[idx[n][m]][h]
// ---------------------------------------------------------------------------
__global__ void bias_gather_kernel(const float* __restrict__ table,
                                   const int* __restrict__ idx) {
    int i = blockIdx.x * blockDim.x + threadIdx.x;   // over N*N = 65536
    if (i < NTOK * NTOK) {
        int t = idx[i];
        #pragma unroll
        for (int h = 0; h < HEADS; h++)
            g_bias[h * (NTOK * NTOK) + i] = table[t * HEADS + h];
    }
}

// ---------------------------------------------------------------------------
// Register-tiled SGEMM (NT):  C[M][N] = A[M][K] @ B[N][K]^T + bias[N]
// BM=BN=128, BK=8, TM=TN=8, 256 threads. M%128==0, N%128==0, K%8==0 assumed.
// ---------------------------------------------------------------------------
__global__ __launch_bounds__(256)
void gemm_nt_bias(const float* __restrict__ A, const float* __restrict__ B,
                  const float* __restrict__ bias, float* __restrict__ C,
                  int M, int N, int K) {
    const int BM = 128, BN = 128, BK = 8, TM = 8, TN = 8;
    __shared__ float As[BK][BM];
    __shared__ float Bs[BK][BN];

    int tid = threadIdx.x;
    int tx = tid % 16;          // col group
    int ty = tid / 16;          // row group
    int bx = blockIdx.x;        // N tile
    int by = blockIdx.y;        // M tile

    const float* Aptr = A + (long)by * BM * K;
    const float* Bptr = B + (long)bx * BN * K;

    int lr = tid >> 1;          // 0..127
    int lk = (tid & 1) * 4;     // 0 or 4

    float acc[TM][TN];
    #pragma unroll
    for (int i = 0; i < TM; i++)
        #pragma unroll
        for (int j = 0; j < TN; j++) acc[i][j] = 0.f;

    for (int k0 = 0; k0 < K; k0 += BK) {
        float4 a4 = *(const float4*)(Aptr + (long)lr * K + k0 + lk);
        float4 b4 = *(const float4*)(Bptr + (long)lr * K + k0 + lk);
        As[lk + 0][lr] = a4.x; As[lk + 1][lr] = a4.y;
        As[lk + 2][lr] = a4.z; As[lk + 3][lr] = a4.w;
        Bs[lk + 0][lr] = b4.x; Bs[lk + 1][lr] = b4.y;
        Bs[lk + 2][lr] = b4.z; Bs[lk + 3][lr] = b4.w;
        __syncthreads();

        #pragma unroll
        for (int k = 0; k < BK; k++) {
            float ra[TM], rb[TN];
            #pragma unroll
            for (int i = 0; i < TM; i++) ra[i] = As[k][ty * TM + i];
            #pragma unroll
            for (int j = 0; j < TN; j++) rb[j] = Bs[k][tx * TN + j];
            #pragma unroll
            for (int i = 0; i < TM; i++)
                #pragma unroll
                for (int j = 0; j < TN; j++)
                    acc[i][j] += ra[i] * rb[j];
        }
        __syncthreads();
    }

    // Epilogue: add bias, float4 stores
    int colBase = bx * BN + tx * TN;
    float bv[TN];
    #pragma unroll
    for (int j = 0; j < TN; j++) bv[j] = bias[colBase + j];

    #pragma unroll
    for (int i = 0; i < TM; i++) {
        long row = (long)by * BM + ty * TM + i;
        float* crow = C + row * N + colBase;
        float4 o0 = make_float4(acc[i][0] + bv[0], acc[i][1] + bv[1],
                                acc[i][2] + bv[2], acc[i][3] + bv[3]);
        float4 o1 = make_float4(acc[i][4] + bv[4], acc[i][5] + bv[5],
                                acc[i][6] + bv[6], acc[i][7] + bv[7]);
        *(float4*)(crow + 0) = o0;
        *(float4*)(crow + 4) = o1;
    }
}

// ---------------------------------------------------------------------------
// Attention: one block per (b, h). 256 threads, thread t = query row t.
// k,v tiles resident in dynamic smem (2 x 32 KB). Softmax without max-
// subtraction (scores bounded well under exp overflow for this problem).
// ---------------------------------------------------------------------------
__global__ __launch_bounds__(256)
void attn_kernel(const float* __restrict__ mask) {
    extern __shared__ float sh[];
    float* ksh = sh;                  // [256][32]
    float* vsh = sh + NTOK * HDIM;    // [256][32]

    int bh = blockIdx.x;
    int b = bh >> 3;
    int h = bh & 7;
    int t = threadIdx.x;              // 0..255 (key row for load, query row for compute)

    const float* base = g_qkv + (long)b * NTOK * (3 * CDIM);

    // load k, v rows for this (b, h)
    const float* krow = base + (long)t * (3 * CDIM) + CDIM + h * HDIM;
    const float* vrow = krow + CDIM;
    #pragma unroll
    for (int d = 0; d < HDIM; d += 4) {
        *(float4*)&ksh[t * HDIM + d] = *(const float4*)(krow + d);
        *(float4*)&vsh[t * HDIM + d] = *(const float4*)(vrow + d);
    }
    __syncthreads();

    // q row into registers (pre-scaled)
    const float scale = 0.17677669529663687f;   // 32^-0.5
    float qreg[HDIM];
    const float* qrow = base + (long)t * (3 * CDIM) + h * HDIM;
    #pragma unroll
    for (int d = 0; d < HDIM; d++) qreg[d] = qrow[d] * scale;

    const float* brow = g_bias + h * (NTOK * NTOK) + t * NTOK;
    const float* mrow = mask + (long)(b & (NWIN - 1)) * (NTOK * NTOK) + t * NTOK;

    float acc[HDIM];
    #pragma unroll
    for (int d = 0; d < HDIM; d++) acc[d] = 0.f;
    float L = 0.f;

    for (int m = 0; m < NTOK; m++) {
        float s = 0.f;
        const float* kr = &ksh[m * HDIM];
        #pragma unroll
        for (int d = 0; d < HDIM; d++) s += qreg[d] * kr[d];
        s += brow[m] + mrow[m];
        float p = __expf(s);
        L += p;
        const float* vr = &vsh[m * HDIM];
        #pragma unroll
        for (int d = 0; d < HDIM; d++) acc[d] += p * vr[d];
    }

    float inv = 1.f / L;
    float* orow = g_attn_out + ((long)(b * NTOK + t)) * CDIM + h * HDIM;
    #pragma unroll
    for (int d = 0; d < HDIM; d += 4) {
        float4 o = make_float4(acc[d] * inv, acc[d + 1] * inv,
                               acc[d + 2] * inv, acc[d + 3] * inv);
        *(float4*)(orow + d) = o;
    }
}

// ---------------------------------------------------------------------------
// Launch
// ---------------------------------------------------------------------------
extern "C" void kernel_launch(void* const* d_in, const int* in_sizes, int n_in,
                              void* d_out, int out_size) {
    const float* x          = (const float*)d_in[0];
    const float* mask       = (const float*)d_in[1];
    const float* qkv_w      = (const float*)d_in[2];
    const float* qkv_b      = (const float*)d_in[3];
    const float* proj_w     = (const float*)d_in[4];
    const float* proj_b     = (const float*)d_in[5];
    const float* rp_table   = (const float*)d_in[6];
    const int*   rp_index   = (const int*)d_in[7];
    float* out = (float*)d_out;

    void* qkv_ptr = nullptr;
    void* attn_ptr = nullptr;
    cudaGetSymbolAddress(&qkv_ptr, g_qkv);
    cudaGetSymbolAddress(&attn_ptr, g_attn_out);
    float* qkv = (float*)qkv_ptr;
    float* attn_out = (float*)attn_ptr;

    // 1) bias gather
    bias_gather_kernel<<<(NTOK * NTOK + 255) / 256, 256>>>(rp_table, rp_index);

    // 2) qkv GEMM: (49152 x 256) @ (768 x 256)^T + qkv_b -> g_qkv
    {
        int M = B_TOT * NTOK, N = 3 * CDIM, K = CDIM;
        dim3 grid(N / 128, M / 128);
        gemm_nt_bias<<<grid, 256>>>(x, qkv_w, qkv_b, qkv, M, N, K);
    }

    // 3) attention
    {
        int smem = 2 * NTOK * HDIM * sizeof(float);   // 64 KB
        cudaFuncSetAttribute(attn_kernel,
                             cudaFuncAttributeMaxDynamicSharedMemorySize, smem);
        attn_kernel<<<B_TOT * HEADS, 256, smem>>>(mask);
    }

    // 4) proj GEMM: (49152 x 256) @ (256 x 256)^T + proj_b -> out
    {
        int M = B_TOT * NTOK, N = CDIM, K = CDIM;
        dim3 grid(N / 128, M / 128);
        gemm_nt_bias<<<grid, 256>>>(attn_out, proj_w, proj_b, out, M, N, K);
    }
}

// round 4
// speedup vs baseline: 1.4103x; 1.4103x over previous
#include <cuda_runtime.h>
#include <cuda_bf16.h>

// ---------------------------------------------------------------------------
// SCC3D window attention block, round 1: vectorized scalar pipeline.
// ---------------------------------------------------------------------------

#define B_TOT   192
#define NTOK    256
#define CDIM    256
#define HEADS   8
#define HDIM    32
#define NWIN    64

// Scratch (device globals: allocation-free)
__device__ float g_qkv[B_TOT * NTOK * 3 * CDIM];       // (B_, N, 3C)
__device__ float g_attn_out[B_TOT * NTOK * CDIM];      // (B_, N, C)
__device__ float g_bias[HEADS * NTOK * NTOK];          // (H, N, N)

// ---------------------------------------------------------------------------
// Bias gather: bias[h][n][m] = table[idx[n][m]][h]
// ---------------------------------------------------------------------------
__global__ void bias_gather_kernel(const float* __restrict__ table,
                                   const int* __restrict__ idx) {
    int i = blockIdx.x * blockDim.x + threadIdx.x;   // over N*N = 65536
    if (i < NTOK * NTOK) {
        int t = idx[i];
        #pragma unroll
        for (int h = 0; h < HEADS; h++)
            g_bias[h * (NTOK * NTOK) + i] = table[t * HEADS + h];
    }
}

// ---------------------------------------------------------------------------
// Register-tiled SGEMM (NT):  C[M][N] = A[M][K] @ B[N][K]^T + bias[N]
// BM=BN=128, BK=16, TM=TN=8, 256 threads, register-prefetch double buffering.
// ---------------------------------------------------------------------------
__global__ __launch_bounds__(256)
void gemm_nt_bias(const float* __restrict__ A, const float* __restrict__ B,
                  const float* __restrict__ bias, float* __restrict__ C,
                  int M, int N, int K) {
    const int BM = 128, BN = 128, BK = 16, TM = 8, TN = 8;
    __shared__ float As[BK][BM];
    __shared__ float Bs[BK][BN];

    int tid = threadIdx.x;
    int tx = tid % 16;          // col group
    int ty = tid / 16;          // row group
    int bx = blockIdx.x;        // N tile
    int by = blockIdx.y;        // M tile

    const float* Aptr = A + (long)by * BM * K;
    const float* Bptr = B + (long)bx * BN * K;

    int lr = tid >> 1;          // 0..127
    int lk = (tid & 1) * 4;     // 0 or 4 (second half at +8)

    float acc[TM][TN];
    #pragma unroll
    for (int i = 0; i < TM; i++)
        #pragma unroll
        for (int j = 0; j < TN; j++) acc[i][j] = 0.f;

    // prefetch first tile
    float4 a0 = *(const float4*)(Aptr + (long)lr * K + lk);
    float4 a1 = *(const float4*)(Aptr + (long)lr * K + lk + 8);
    float4 b0 = *(const float4*)(Bptr + (long)lr * K + lk);
    float4 b1 = *(const float4*)(Bptr + (long)lr * K + lk + 8);

    for (int k0 = 0; k0 < K; k0 += BK) {
        As[lk + 0][lr] = a0.x; As[lk + 1][lr] = a0.y;
        As[lk + 2][lr] = a0.z; As[lk + 3][lr] = a0.w;
        As[lk + 8][lr] = a1.x; As[lk + 9][lr] = a1.y;
        As[lk +10][lr] = a1.z; As[lk +11][lr] = a1.w;
        Bs[lk + 0][lr] = b0.x; Bs[lk + 1][lr] = b0.y;
        Bs[lk + 2][lr] = b0.z; Bs[lk + 3][lr] = b0.w;
        Bs[lk + 8][lr] = b1.x; Bs[lk + 9][lr] = b1.y;
        Bs[lk +10][lr] = b1.z; Bs[lk +11][lr] = b1.w;
        __syncthreads();

        if (k0 + BK < K) {
            a0 = *(const float4*)(Aptr + (long)lr * K + k0 + BK + lk);
            a1 = *(const float4*)(Aptr + (long)lr * K + k0 + BK + lk + 8);
            b0 = *(const float4*)(Bptr + (long)lr * K + k0 + BK + lk);
            b1 = *(const float4*)(Bptr + (long)lr * K + k0 + BK + lk + 8);
        }

        #pragma unroll
        for (int k = 0; k < BK; k++) {
            float ra[TM], rb[TN];
            #pragma unroll
            for (int i = 0; i < TM; i += 4)
                *(float4*)&ra[i] = *(const float4*)&As[k][ty * TM + i];
            #pragma unroll
            for (int j = 0; j < TN; j += 4)
                *(float4*)&rb[j] = *(const float4*)&Bs[k][tx * TN + j];
            #pragma unroll
            for (int i = 0; i < TM; i++)
                #pragma unroll
                for (int j = 0; j < TN; j++)
                    acc[i][j] += ra[i] * rb[j];
        }
        __syncthreads();
    }

    // Epilogue: add bias, float4 stores
    int colBase = bx * BN + tx * TN;
    float bv[TN];
    #pragma unroll
    for (int j = 0; j < TN; j += 4)
        *(float4*)&bv[j] = *(const float4*)(bias + colBase + j);

    #pragma unroll
    for (int i = 0; i < TM; i++) {
        long row = (long)by * BM + ty * TM + i;
        float* crow = C + row * N + colBase;
        float4 o0 = make_float4(acc[i][0] + bv[0], acc[i][1] + bv[1],
                                acc[i][2] + bv[2], acc[i][3] + bv[3]);
        float4 o1 = make_float4(acc[i][4] + bv[4], acc[i][5] + bv[5],
                                acc[i][6] + bv[6], acc[i][7] + bv[7]);
        *(float4*)(crow + 0) = o0;
        *(float4*)(crow + 4) = o1;
    }
}

// ---------------------------------------------------------------------------
// Attention: one block per (b, h). 256 threads, thread t = query row t.
// k,v resident in dynamic smem (2 x 32 KB), all accesses float4.
// ---------------------------------------------------------------------------
__global__ __launch_bounds__(256)
void attn_kernel(const float* __restrict__ mask) {
    extern __shared__ float sh[];
    float* ksh = sh;                  // [256][32]
    float* vsh = sh + NTOK * HDIM;    // [256][32]

    int bh = blockIdx.x;
    int b = bh >> 3;
    int h = bh & 7;
    int t = threadIdx.x;

    const float* base = g_qkv + (long)b * NTOK * (3 * CDIM);

    // load k, v rows for this (b, h)
    const float* krow = base + (long)t * (3 * CDIM) + CDIM + h * HDIM;
    const float* vrow = krow + CDIM;
    #pragma unroll
    for (int d = 0; d < HDIM; d += 4) {
        *(float4*)&ksh[t * HDIM + d] = *(const float4*)(krow + d);
        *(float4*)&vsh[t * HDIM + d] = *(const float4*)(vrow + d);
    }
    __syncthreads();

    // q row into float4 registers (pre-scaled)
    const float scale = 0.17677669529663687f;   // 32^-0.5
    float4 q4[8];
    const float* qrow = base + (long)t * (3 * CDIM) + h * HDIM;
    #pragma unroll
    for (int i = 0; i < 8; i++) {
        float4 qv = *(const float4*)(qrow + 4 * i);
        q4[i] = make_float4(qv.x * scale, qv.y * scale, qv.z * scale, qv.w * scale);
    }

    const float4* b4p = (const float4*)(g_bias + h * (NTOK * NTOK) + t * NTOK);
    const float4* m4p = (const float4*)(mask + (long)(b & (NWIN - 1)) * (NTOK * NTOK) + t * NTOK);

    float4 acc4[8];
    #pragma unroll
    for (int i = 0; i < 8; i++) acc4[i] = make_float4(0.f, 0.f, 0.f, 0.f);
    float L = 0.f;

    for (int mq = 0; mq < NTOK / 4; mq++) {
        float4 bb = b4p[mq];
        float4 mm = m4p[mq];
        float sb[4] = {bb.x + mm.x, bb.y + mm.y, bb.z + mm.z, bb.w + mm.w};

        #pragma unroll
        for (int j = 0; j < 4; j++) {
            int m = mq * 4 + j;
            const float4* kr = (const float4*)&ksh[m * HDIM];
            float s = sb[j];
            #pragma unroll
            for (int i = 0; i < 8; i++) {
                float4 kk = kr[i];
                s += q4[i].x * kk.x + q4[i].y * kk.y + q4[i].z * kk.z + q4[i].w * kk.w;
            }
            float p = __expf(s);
            L += p;
            const float4* vr = (const float4*)&vsh[m * HDIM];
            #pragma unroll
            for (int i = 0; i < 8; i++) {
                float4 vv = vr[i];
                acc4[i].x += p * vv.x; acc4[i].y += p * vv.y;
                acc4[i].z += p * vv.z; acc4[i].w += p * vv.w;
            }
        }
    }

    float inv = 1.f / L;
    float* orow = g_attn_out + ((long)(b * NTOK + t)) * CDIM + h * HDIM;
    #pragma unroll
    for (int i = 0; i < 8; i++) {
        float4 o = make_float4(acc4[i].x * inv, acc4[i].y * inv,
                               acc4[i].z * inv, acc4[i].w * inv);
        *(float4*)(orow + 4 * i) = o;
    }
}

// ---------------------------------------------------------------------------
// Launch
// ---------------------------------------------------------------------------
extern "C" void kernel_launch(void* const* d_in, const int* in_sizes, int n_in,
                              void* d_out, int out_size) {
    const float* x          = (const float*)d_in[0];
    const float* mask       = (const float*)d_in[1];
    const float* qkv_w      = (const float*)d_in[2];
    const float* qkv_b      = (const float*)d_in[3];
    const float* proj_w     = (const float*)d_in[4];
    const float* proj_b     = (const float*)d_in[5];
    const float* rp_table   = (const float*)d_in[6];
    const int*   rp_index   = (const int*)d_in[7];
    float* out = (float*)d_out;

    void* qkv_ptr = nullptr;
    void* attn_ptr = nullptr;
    cudaGetSymbolAddress(&qkv_ptr, g_qkv);
    cudaGetSymbolAddress(&attn_ptr, g_attn_out);
    float* qkv = (float*)qkv_ptr;
    float* attn_out = (float*)attn_ptr;

    // 1) bias gather
    bias_gather_kernel<<<(NTOK * NTOK + 255) / 256, 256>>>(rp_table, rp_index);

    // 2) qkv GEMM: (49152 x 256) @ (768 x 256)^T + qkv_b -> g_qkv
    {
        int M = B_TOT * NTOK, N = 3 * CDIM, K = CDIM;
        dim3 grid(N / 128, M / 128);
        gemm_nt_bias<<<grid, 256>>>(x, qkv_w, qkv_b, qkv, M, N, K);
    }

    // 3) attention
    {
        int smem = 2 * NTOK * HDIM * sizeof(float);   // 64 KB
        cudaFuncSetAttribute(attn_kernel,
                             cudaFuncAttributeMaxDynamicSharedMemorySize, smem);
        attn_kernel<<<B_TOT * HEADS, 256, smem>>>(mask);
    }

    // 4) proj GEMM: (49152 x 256) @ (256 x 256)^T + proj_b -> out
    {
        int M = B_TOT * NTOK, N = CDIM, K = CDIM;
        dim3 grid(N / 128, M / 128);
        gemm_nt_bias<<<grid, 256>>>(attn_out, proj_w, proj_b, out, M, N, K);
    }
}

// round 7
// speedup vs baseline: 2.0086x; 1.4242x over previous
#include <cuda_runtime.h>
#include <cstdint>

// ---------------------------------------------------------------------------
// SCC3D window attention block, round 6:
//   mma.sync tf32 GEMMs (family-safe tensor core path) + scalar attention.
// ---------------------------------------------------------------------------

#define B_TOT   192
#define NTOK    256
#define CDIM    256
#define HEADS   8
#define HDIM    32
#define NWIN    64

// Scratch (device globals: allocation-free)
__device__ float g_qkv[B_TOT * NTOK * 3 * CDIM];       // (B_, N, 3C)
__device__ float g_attn_out[B_TOT * NTOK * CDIM];      // (B_, N, C) tf32-rounded
__device__ float g_bias[HEADS * NTOK * NTOK];          // (H, N, N)
__device__ float g_xr[B_TOT * NTOK * CDIM];            // tf32-rounded x
__device__ float g_wq[3 * CDIM * CDIM];                // tf32-rounded qkv_w
__device__ float g_wp[CDIM * CDIM];                    // tf32-rounded proj_w

// ---------------------------------------------------------------------------
// Helpers
// ---------------------------------------------------------------------------
__device__ __forceinline__ uint32_t smem_u32(const void* p) {
    uint32_t a;
    asm("{ .reg .u64 t; cvta.to.shared.u64 t, %1; cvt.u32.u64 %0, t; }"
        : "=r"(a) : "l"(p));
    return a;
}

__device__ __forceinline__ float tf32_rn(float x) {
    uint32_t u;
    asm("cvt.rna.tf32.f32 %0, %1;" : "=r"(u) : "f"(x));
    return __uint_as_float(u);
}

#define CP_ASYNC16(dst, src) \
    asm volatile("cp.async.cg.shared.global [%0], [%1], 16;" :: "r"(dst), "l"(src) : "memory")
#define CP_COMMIT() asm volatile("cp.async.commit_group;" ::: "memory")
#define CP_WAIT(n)  asm volatile("cp.async.wait_group %0;" :: "n"(n) : "memory")

__device__ __forceinline__ void mma_tf32_16x8x8(float* d, const uint32_t* a,
                                                const uint32_t* b) {
    asm volatile(
        "mma.sync.aligned.m16n8k8.row.col.f32.tf32.tf32.f32 "
        "{%0,%1,%2,%3}, {%4,%5,%6,%7}, {%8,%9}, {%0,%1,%2,%3};"
        : "+f"(d[0]), "+f"(d[1]), "+f"(d[2]), "+f"(d[3])
        : "r"(a[0]), "r"(a[1]), "r"(a[2]), "r"(a[3]), "r"(b[0]), "r"(b[1]));
}

// ---------------------------------------------------------------------------
// Elementwise tf32 round (RNA) pass
// ---------------------------------------------------------------------------
__global__ void round_tf32_kernel(const float4* __restrict__ in,
                                  float4* __restrict__ out, int n4) {
    int i = blockIdx.x * blockDim.x + threadIdx.x;
    if (i < n4) {
        float4 v = in[i];
        v.x = tf32_rn(v.x); v.y = tf32_rn(v.y);
        v.z = tf32_rn(v.z); v.w = tf32_rn(v.w);
        out[i] = v;
    }
}

// ---------------------------------------------------------------------------
// Bias gather: bias[h][n][m] = table[idx[n][m]][h]
// ---------------------------------------------------------------------------
__global__ void bias_gather_kernel(const float* __restrict__ table,
                                   const int* __restrict__ idx) {
    int i = blockIdx.x * blockDim.x + threadIdx.x;
    if (i < NTOK * NTOK) {
        int t = idx[i];
        #pragma unroll
        for (int h = 0; h < HEADS; h++)
            g_bias[h * (NTOK * NTOK) + i] = table[t * HEADS + h];
    }
}

// ---------------------------------------------------------------------------
// mma.sync tf32 GEMM (NT): C[M][N] = A[M][K] @ B[N][K]^T + bias[N]
// Block 128x128, BK=32, 256 threads (8 warps, 2x4), warp tile 64x32.
// cp.async double-buffered smem, stride-36 rows (conflict-free frag LDS).
// Inputs must be pre-rounded to tf32. grid = (N/128, M/128).
// ---------------------------------------------------------------------------
#define LDROW 36                      // floats per smem row (pad 32 -> 36)
#define TILE_F (128 * LDROW)          // 4608 floats per tile buffer

__global__ __launch_bounds__(256)
void gemm_tf32(const float* __restrict__ A, const float* __restrict__ B,
               const float* __restrict__ bias, float* __restrict__ C,
               int N, int K) {
    extern __shared__ float sh[];
    // layout: sA0 | sA1 | sB0 | sB1, each TILE_F floats
    float* sAb[2] = { sh, sh + TILE_F };
    float* sBb[2] = { sh + 2 * TILE_F, sh + 3 * TILE_F };

    int tid = threadIdx.x;
    int w = tid >> 5, lane = tid & 31;
    int wm = w & 1, wn = w >> 1;      // 2 warps in M, 4 in N
    int lr = lane >> 2, lc = lane & 3;
    int bx = blockIdx.x, by = blockIdx.y;

    const float* Ap = A + (size_t)by * 128 * K;
    const float* Bp = B + (size_t)bx * 128 * K;

    int f = tid & 7;                  // float4 column 0..7
    int r0 = tid >> 3;                // row 0..31 (each thread: 4 rows stride 32)

    float acc[4][4][4];
    #pragma unroll
    for (int mf = 0; mf < 4; mf++)
        #pragma unroll
        for (int nf = 0; nf < 4; nf++)
            #pragma unroll
            for (int q = 0; q < 4; q++) acc[mf][nf][q] = 0.f;

    const int NCH = K >> 5;

    // issue cp.async for chunk c into buffer buf
    #define ISSUE(c, buf)                                                     \
        {                                                                     \
            _Pragma("unroll")                                                 \
            for (int i = 0; i < 4; i++) {                                     \
                int row = r0 + 32 * i;                                        \
                CP_ASYNC16(smem_u32(&sAb[buf][row * LDROW + f * 4]),          \
                           Ap + (size_t)row * K + (c) * 32 + f * 4);          \
                CP_ASYNC16(smem_u32(&sBb[buf][row * LDROW + f * 4]),          \
                           Bp + (size_t)row * K + (c) * 32 + f * 4);          \
            }                                                                 \
            CP_COMMIT();                                                      \
        }

    ISSUE(0, 0);

    for (int c = 0; c < NCH; c++) {
        if (c + 1 < NCH) {
            ISSUE(c + 1, (c + 1) & 1);
            CP_WAIT(1);
        } else {
            CP_WAIT(0);
        }
        __syncthreads();

        const float* As = sAb[c & 1];
        const float* Bs = sBb[c & 1];

        #pragma unroll
        for (int ks = 0; ks < 4; ks++) {
            int k0 = ks * 8;
            uint32_t af[4][4], bf[4][2];
            #pragma unroll
            for (int mf = 0; mf < 4; mf++) {
                int rb = wm * 64 + mf * 16 + lr;
                af[mf][0] = __float_as_uint(As[rb * LDROW + k0 + lc]);
                af[mf][1] = __float_as_uint(As[(rb + 8) * LDROW + k0 + lc]);
                af[mf][2] = __float_as_uint(As[rb * LDROW + k0 + lc + 4]);
                af[mf][3] = __float_as_uint(As[(rb + 8) * LDROW + k0 + lc + 4]);
            }
            #pragma unroll
            for (int nf = 0; nf < 4; nf++) {
                int nb = wn * 32 + nf * 8 + lr;
                bf[nf][0] = __float_as_uint(Bs[nb * LDROW + k0 + lc]);
                bf[nf][1] = __float_as_uint(Bs[nb * LDROW + k0 + lc + 4]);
            }
            #pragma unroll
            for (int mf = 0; mf < 4; mf++)
                #pragma unroll
                for (int nf = 0; nf < 4; nf++)
                    mma_tf32_16x8x8(acc[mf][nf], af[mf], bf[nf]);
        }
        __syncthreads();
    }

    // epilogue: add bias, float2 stores
    #pragma unroll
    for (int mf = 0; mf < 4; mf++) {
        size_t row0 = (size_t)by * 128 + wm * 64 + mf * 16 + lr;
        #pragma unroll
        for (int nf = 0; nf < 4; nf++) {
            int col = bx * 128 + wn * 32 + nf * 8 + 2 * lc;
            float bx0 = bias[col], bx1 = bias[col + 1];
            float2 o0 = make_float2(acc[mf][nf][0] + bx0, acc[mf][nf][1] + bx1);
            float2 o1 = make_float2(acc[mf][nf][2] + bx0, acc[mf][nf][3] + bx1);
            *(float2*)(C + row0 * N + col) = o0;
            *(float2*)(C + (row0 + 8) * N + col) = o1;
        }
    }
}

// ---------------------------------------------------------------------------
// Attention: one block per (b, h). 256 threads, thread t = query row t.
// Output rounded to tf32 (feeds tf32 proj GEMM).
// ---------------------------------------------------------------------------
__global__ __launch_bounds__(256)
void attn_kernel(const float* __restrict__ mask) {
    extern __shared__ float sh[];
    float* ksh = sh;                  // [256][32]
    float* vsh = sh + NTOK * HDIM;    // [256][32]

    int bh = blockIdx.x;
    int b = bh >> 3;
    int h = bh & 7;
    int t = threadIdx.x;

    const float* base = g_qkv + (size_t)b * NTOK * (3 * CDIM);

    const float* krow = base + (size_t)t * (3 * CDIM) + CDIM + h * HDIM;
    const float* vrow = krow + CDIM;
    #pragma unroll
    for (int d = 0; d < HDIM; d += 4) {
        *(float4*)&ksh[t * HDIM + d] = *(const float4*)(krow + d);
        *(float4*)&vsh[t * HDIM + d] = *(const float4*)(vrow + d);
    }
    __syncthreads();

    const float scale = 0.17677669529663687f;   // 32^-0.5
    float4 q4[8];
    const float* qrow = base + (size_t)t * (3 * CDIM) + h * HDIM;
    #pragma unroll
    for (int i = 0; i < 8; i++) {
        float4 qv = *(const float4*)(qrow + 4 * i);
        q4[i] = make_float4(qv.x * scale, qv.y * scale, qv.z * scale, qv.w * scale);
    }

    const float4* b4p = (const float4*)(g_bias + h * (NTOK * NTOK) + t * NTOK);
    const float4* m4p = (const float4*)(mask + (size_t)(b & (NWIN - 1)) * (NTOK * NTOK) + t * NTOK);

    float4 acc4[8];
    #pragma unroll
    for (int i = 0; i < 8; i++) acc4[i] = make_float4(0.f, 0.f, 0.f, 0.f);
    float L = 0.f;

    for (int mq = 0; mq < NTOK / 4; mq++) {
        float4 bb = b4p[mq];
        float4 mm = m4p[mq];
        float sb[4] = {bb.x + mm.x, bb.y + mm.y, bb.z + mm.z, bb.w + mm.w};

        #pragma unroll
        for (int j = 0; j < 4; j++) {
            int m = mq * 4 + j;
            const float4* kr = (const float4*)&ksh[m * HDIM];
            float s = sb[j];
            #pragma unroll
            for (int i = 0; i < 8; i++) {
                float4 kk = kr[i];
                s += q4[i].x * kk.x + q4[i].y * kk.y + q4[i].z * kk.z + q4[i].w * kk.w;
            }
            float p = __expf(s);
            L += p;
            const float4* vr = (const float4*)&vsh[m * HDIM];
            #pragma unroll
            for (int i = 0; i < 8; i++) {
                float4 vv = vr[i];
                acc4[i].x += p * vv.x; acc4[i].y += p * vv.y;
                acc4[i].z += p * vv.z; acc4[i].w += p * vv.w;
            }
        }
    }

    float inv = 1.f / L;
    float* orow = g_attn_out + ((size_t)(b * NTOK + t)) * CDIM + h * HDIM;
    #pragma unroll
    for (int i = 0; i < 8; i++) {
        float4 o = make_float4(tf32_rn(acc4[i].x * inv), tf32_rn(acc4[i].y * inv),
                               tf32_rn(acc4[i].z * inv), tf32_rn(acc4[i].w * inv));
        *(float4*)(orow + 4 * i) = o;
    }
}

// ---------------------------------------------------------------------------
// Launch
// ---------------------------------------------------------------------------
extern "C" void kernel_launch(void* const* d_in, const int* in_sizes, int n_in,
                              void* d_out, int out_size) {
    const float* x          = (const float*)d_in[0];
    const float* mask       = (const float*)d_in[1];
    const float* qkv_w      = (const float*)d_in[2];
    const float* qkv_b      = (const float*)d_in[3];
    const float* proj_w     = (const float*)d_in[4];
    const float* proj_b     = (const float*)d_in[5];
    const float* rp_table   = (const float*)d_in[6];
    const int*   rp_index   = (const int*)d_in[7];
    float* out = (float*)d_out;

    void *p_qkv, *p_attn, *p_xr, *p_wq, *p_wp;
    cudaGetSymbolAddress(&p_qkv, g_qkv);
    cudaGetSymbolAddress(&p_attn, g_attn_out);
    cudaGetSymbolAddress(&p_xr, g_xr);
    cudaGetSymbolAddress(&p_wq, g_wq);
    cudaGetSymbolAddress(&p_wp, g_wp);
    float* qkv = (float*)p_qkv;
    float* attn_out = (float*)p_attn;
    float* xr = (float*)p_xr;
    float* wq = (float*)p_wq;
    float* wp = (float*)p_wp;

    const int gemm_smem = 4 * TILE_F * sizeof(float);   // 73,728 B
    cudaFuncSetAttribute(gemm_tf32,
                         cudaFuncAttributeMaxDynamicSharedMemorySize, gemm_smem);

    // 1) bias gather + tf32 rounding of GEMM inputs
    bias_gather_kernel<<<(NTOK * NTOK + 255) / 256, 256>>>(rp_table, rp_index);
    {
        int n4 = B_TOT * NTOK * CDIM / 4;
        round_tf32_kernel<<<(n4 + 255) / 256, 256>>>((const float4*)x, (float4*)xr, n4);
    }
    {
        int n4 = 3 * CDIM * CDIM / 4;
        round_tf32_kernel<<<(n4 + 255) / 256, 256>>>((const float4*)qkv_w, (float4*)wq, n4);
    }
    {
        int n4 = CDIM * CDIM / 4;
        round_tf32_kernel<<<(n4 + 255) / 256, 256>>>((const float4*)proj_w, (float4*)wp, n4);
    }

    // 2) qkv GEMM: (49152 x 256) @ (768 x 256)^T + qkv_b -> g_qkv
    {
        int M = B_TOT * NTOK, N = 3 * CDIM, K = CDIM;
        dim3 grid(N / 128, M / 128);
        gemm_tf32<<<grid, 256, gemm_smem>>>(xr, wq, qkv_b, qkv, N, K);
    }

    // 3) attention
    {
        int smem = 2 * NTOK * HDIM * sizeof(float);   // 64 KB
        cudaFuncSetAttribute(attn_kernel,
                             cudaFuncAttributeMaxDynamicSharedMemorySize, smem);
        attn_kernel<<<B_TOT * HEADS, 256, smem>>>(mask);
    }

    // 4) proj GEMM: (49152 x 256) @ (256 x 256)^T + proj_b -> out
    {
        int M = B_TOT * NTOK, N = CDIM, K = CDIM;
        dim3 grid(N / 128, M / 128);
        gemm_tf32<<<grid, 256, gemm_smem>>>(attn_out, wp, proj_b, out, N, K);
    }
}

// round 9
// speedup vs baseline: 3.2527x; 1.6194x over previous
#include <cuda_runtime.h>
#include <cstdint>

// ---------------------------------------------------------------------------
// SCC3D window attention block, round 7:
//   mma.sync tf32 GEMMs + mma.sync tf32 fused attention.
// ---------------------------------------------------------------------------

#define B_TOT   192
#define NTOK    256
#define CDIM    256
#define HEADS   8
#define HDIM    32
#define NWIN    64

// Scratch (device globals: allocation-free)
__device__ float g_qkv[B_TOT * NTOK * 3 * CDIM];       // (B_, N, 3C) tf32-rounded
__device__ float g_attn_out[B_TOT * NTOK * CDIM];      // (B_, N, C) tf32-rounded
__device__ float g_bias[HEADS * NTOK * NTOK];          // (H, N, N)
__device__ float g_xr[B_TOT * NTOK * CDIM];            // tf32-rounded x
__device__ float g_wq[3 * CDIM * CDIM];                // tf32-rounded qkv_w
__device__ float g_wp[CDIM * CDIM];                    // tf32-rounded proj_w

// ---------------------------------------------------------------------------
// Helpers
// ---------------------------------------------------------------------------
__device__ __forceinline__ uint32_t smem_u32(const void* p) {
    uint32_t a;
    asm("{ .reg .u64 t; cvta.to.shared.u64 t, %1; cvt.u32.u64 %0, t; }"
        : "=r"(a) : "l"(p));
    return a;
}

__device__ __forceinline__ float tf32_rn(float x) {
    uint32_t u;
    asm("cvt.rna.tf32.f32 %0, %1;" : "=r"(u) : "f"(x));
    return __uint_as_float(u);
}

#define CP_ASYNC16(dst, src) \
    asm volatile("cp.async.cg.shared.global [%0], [%1], 16;" :: "r"(dst), "l"(src) : "memory")
#define CP_COMMIT() asm volatile("cp.async.commit_group;" ::: "memory")
#define CP_WAIT(n)  asm volatile("cp.async.wait_group %0;" :: "n"(n) : "memory")

__device__ __forceinline__ void mma_tf32_16x8x8(float* d, const uint32_t* a,
                                                const uint32_t* b) {
    asm volatile(
        "mma.sync.aligned.m16n8k8.row.col.f32.tf32.tf32.f32 "
        "{%0,%1,%2,%3}, {%4,%5,%6,%7}, {%8,%9}, {%0,%1,%2,%3};"
        : "+f"(d[0]), "+f"(d[1]), "+f"(d[2]), "+f"(d[3])
        : "r"(a[0]), "r"(a[1]), "r"(a[2]), "r"(a[3]), "r"(b[0]), "r"(b[1]));
}

// ---------------------------------------------------------------------------
// Elementwise tf32 round (RNA) pass
// ---------------------------------------------------------------------------
__global__ void round_tf32_kernel(const float4* __restrict__ in,
                                  float4* __restrict__ out, int n4) {
    int i = blockIdx.x * blockDim.x + threadIdx.x;
    if (i < n4) {
        float4 v = in[i];
        v.x = tf32_rn(v.x); v.y = tf32_rn(v.y);
        v.z = tf32_rn(v.z); v.w = tf32_rn(v.w);
        out[i] = v;
    }
}

// ---------------------------------------------------------------------------
// Bias gather: bias[h][n][m] = table[idx[n][m]][h]
// ---------------------------------------------------------------------------
__global__ void bias_gather_kernel(const float* __restrict__ table,
                                   const int* __restrict__ idx) {
    int i = blockIdx.x * blockDim.x + threadIdx.x;
    if (i < NTOK * NTOK) {
        int t = idx[i];
        #pragma unroll
        for (int h = 0; h < HEADS; h++)
            g_bias[h * (NTOK * NTOK) + i] = table[t * HEADS + h];
    }
}

// ---------------------------------------------------------------------------
// mma.sync tf32 GEMM (NT): C[M][N] = A[M][K] @ B[N][K]^T + bias[N]
// Block 128x128, BK=32, 256 threads (8 warps 2x4), warp tile 64x32.
// round_out != 0: RNA-round output to tf32 (for qkv GEMM feeding attention).
// ---------------------------------------------------------------------------
#define LDROW 36
#define TILE_F (128 * LDROW)

__global__ __launch_bounds__(256)
void gemm_tf32(const float* __restrict__ A, const float* __restrict__ B,
               const float* __restrict__ bias, float* __restrict__ C,
               int N, int K, int round_out) {
    extern __shared__ float sh[];
    float* sAb[2] = { sh, sh + TILE_F };
    float* sBb[2] = { sh + 2 * TILE_F, sh + 3 * TILE_F };

    int tid = threadIdx.x;
    int w = tid >> 5, lane = tid & 31;
    int wm = w & 1, wn = w >> 1;
    int lr = lane >> 2, lc = lane & 3;
    int bx = blockIdx.x, by = blockIdx.y;

    const float* Ap = A + (size_t)by * 128 * K;
    const float* Bp = B + (size_t)bx * 128 * K;

    int f = tid & 7;
    int r0 = tid >> 3;

    float acc[4][4][4];
    #pragma unroll
    for (int mf = 0; mf < 4; mf++)
        #pragma unroll
        for (int nf = 0; nf < 4; nf++)
            #pragma unroll
            for (int q = 0; q < 4; q++) acc[mf][nf][q] = 0.f;

    const int NCH = K >> 5;

    #define ISSUE(c, buf)                                                     \
        {                                                                     \
            _Pragma("unroll")                                                 \
            for (int i = 0; i < 4; i++) {                                     \
                int row = r0 + 32 * i;                                        \
                CP_ASYNC16(smem_u32(&sAb[buf][row * LDROW + f * 4]),          \
                           Ap + (size_t)row * K + (c) * 32 + f * 4);          \
                CP_ASYNC16(smem_u32(&sBb[buf][row * LDROW + f * 4]),          \
                           Bp + (size_t)row * K + (c) * 32 + f * 4);          \
            }                                                                 \
            CP_COMMIT();                                                      \
        }

    ISSUE(0, 0);

    for (int c = 0; c < NCH; c++) {
        if (c + 1 < NCH) {
            ISSUE(c + 1, (c + 1) & 1);
            CP_WAIT(1);
        } else {
            CP_WAIT(0);
        }
        __syncthreads();

        const float* As = sAb[c & 1];
        const float* Bs = sBb[c & 1];

        #pragma unroll
        for (int ks = 0; ks < 4; ks++) {
            int k0 = ks * 8;
            uint32_t af[4][4], bf[4][2];
            #pragma unroll
            for (int mf = 0; mf < 4; mf++) {
                int rb = wm * 64 + mf * 16 + lr;
                af[mf][0] = __float_as_uint(As[rb * LDROW + k0 + lc]);
                af[mf][1] = __float_as_uint(As[(rb + 8) * LDROW + k0 + lc]);
                af[mf][2] = __float_as_uint(As[rb * LDROW + k0 + lc + 4]);
                af[mf][3] = __float_as_uint(As[(rb + 8) * LDROW + k0 + lc + 4]);
            }
            #pragma unroll
            for (int nf = 0; nf < 4; nf++) {
                int nb = wn * 32 + nf * 8 + lr;
                bf[nf][0] = __float_as_uint(Bs[nb * LDROW + k0 + lc]);
                bf[nf][1] = __float_as_uint(Bs[nb * LDROW + k0 + lc + 4]);
            }
            #pragma unroll
            for (int mf = 0; mf < 4; mf++)
                #pragma unroll
                for (int nf = 0; nf < 4; nf++)
                    mma_tf32_16x8x8(acc[mf][nf], af[mf], bf[nf]);
        }
        __syncthreads();
    }

    #pragma unroll
    for (int mf = 0; mf < 4; mf++) {
        size_t row0 = (size_t)by * 128 + wm * 64 + mf * 16 + lr;
        #pragma unroll
        for (int nf = 0; nf < 4; nf++) {
            int col = bx * 128 + wn * 32 + nf * 8 + 2 * lc;
            float bx0 = bias[col], bx1 = bias[col + 1];
            float v0 = acc[mf][nf][0] + bx0, v1 = acc[mf][nf][1] + bx1;
            float v2 = acc[mf][nf][2] + bx0, v3 = acc[mf][nf][3] + bx1;
            if (round_out) {
                v0 = tf32_rn(v0); v1 = tf32_rn(v1);
                v2 = tf32_rn(v2); v3 = tf32_rn(v3);
            }
            *(float2*)(C + row0 * N + col) = make_float2(v0, v1);
            *(float2*)(C + (row0 + 8) * N + col) = make_float2(v2, v3);
        }
    }
}

// ---------------------------------------------------------------------------
// Fused attention via mma.sync tf32. One block per (b, h), 8 warps.
// Warp owns 32 query rows. K/V staged in smem; key chunks of 32:
//   S = Q K^T (MMA) -> scale + bias + mask + exp -> P (tf32 RNA, via smem)
//   O += P V (MMA). L accumulated per lane, quad-reduced at the end.
// ---------------------------------------------------------------------------
#define KPAD 36
#define VPAD 40
#define PPAD 36
#define ATTN_SMEM ((NTOK*KPAD + NTOK*VPAD + 8*32*PPAD) * 4)

__global__ __launch_bounds__(256)
void attn_mma(const float* __restrict__ mask) {
    extern __shared__ float sh[];
    float* ksh = sh;                         // [256][KPAD]
    float* vsh = sh + NTOK * KPAD;           // [256][VPAD]

    int tid = threadIdx.x;
    int wid = tid >> 5, lane = tid & 31;
    int lr = lane >> 2, lc = lane & 3;
    float* psh = sh + NTOK * KPAD + NTOK * VPAD + wid * (32 * PPAD);

    int bh = blockIdx.x;
    int b = bh >> 3, h = bh & 7;
    const float* base = g_qkv + (size_t)b * NTOK * (3 * CDIM);

    // stage K, V (thread t -> token t)
    {
        const float* kr = base + (size_t)tid * (3 * CDIM) + CDIM + h * HDIM;
        const float* vr = kr + CDIM;
        #pragma unroll
        for (int i = 0; i < 8; i++) {
            *(float4*)&ksh[tid * KPAD + 4 * i] = *(const float4*)(kr + 4 * i);
            *(float4*)&vsh[tid * VPAD + 4 * i] = *(const float4*)(vr + 4 * i);
        }
    }
    // stage this warp's 32 Q rows into its psh region (lane = local row)
    {
        const float* qr = base + (size_t)(wid * 32 + lane) * (3 * CDIM) + h * HDIM;
        #pragma unroll
        for (int i = 0; i < 8; i++)
            *(float4*)&psh[lane * PPAD + 4 * i] = *(const float4*)(qr + 4 * i);
    }
    __syncthreads();

    // Q fragments (A operand), raw (scale applied post-MMA)
    uint32_t aq[2][4][4];
    #pragma unroll
    for (int mf = 0; mf < 2; mf++)
        #pragma unroll
        for (int ks = 0; ks < 4; ks++) {
            int rb = mf * 16 + lr;
            aq[mf][ks][0] = __float_as_uint(psh[rb * PPAD + 8 * ks + lc]);
            aq[mf][ks][1] = __float_as_uint(psh[(rb + 8) * PPAD + 8 * ks + lc]);
            aq[mf][ks][2] = __float_as_uint(psh[rb * PPAD + 8 * ks + lc + 4]);
            aq[mf][ks][3] = __float_as_uint(psh[(rb + 8) * PPAD + 8 * ks + lc + 4]);
        }
    __syncwarp();

    float o[2][4][4];
    #pragma unroll
    for (int mf = 0; mf < 2; mf++)
        #pragma unroll
        for (int nf = 0; nf < 4; nf++)
            #pragma unroll
            for (int q = 0; q < 4; q++) o[mf][nf][q] = 0.f;
    float Lp[2][2] = {{0.f, 0.f}, {0.f, 0.f}};

    const float scale = 0.17677669529663687f;   // 32^-0.5
    const float* bias_b = g_bias + h * (NTOK * NTOK);
    const float* mask_b = mask + (size_t)(b & (NWIN - 1)) * (NTOK * NTOK);

    for (int c = 0; c < 8; c++) {
        int kb = c * 32;
        float s[2][4][4];
        #pragma unroll
        for (int mf = 0; mf < 2; mf++)
            #pragma unroll
            for (int nf = 0; nf < 4; nf++)
                #pragma unroll
                for (int q = 0; q < 4; q++) s[mf][nf][q] = 0.f;

        // S = Q K^T over d (4 k-steps of 8)
        #pragma unroll
        for (int ks = 0; ks < 4; ks++) {
            uint32_t bk[4][2];
            #pragma unroll
            for (int nf = 0; nf < 4; nf++) {
                int key = kb + nf * 8 + lr;
                bk[nf][0] = __float_as_uint(ksh[key * KPAD + 8 * ks + lc]);
                bk[nf][1] = __float_as_uint(ksh[key * KPAD + 8 * ks + lc + 4]);
            }
            #pragma unroll
            for (int mf = 0; mf < 2; mf++)
                #pragma unroll
                for (int nf = 0; nf < 4; nf++)
                    mma_tf32_16x8x8(s[mf][nf], aq[mf][ks], bk[nf]);
        }

        // scale + bias + mask + exp; store P (tf32 RNA) to psh
        #pragma unroll
        for (int mf = 0; mf < 2; mf++) {
            int q0 = wid * 32 + mf * 16 + lr;
            #pragma unroll
            for (int nf = 0; nf < 4; nf++) {
                int col = kb + nf * 8 + 2 * lc;
                float2 b0 = *(const float2*)(bias_b + (size_t)q0 * NTOK + col);
                float2 b1 = *(const float2*)(bias_b + (size_t)(q0 + 8) * NTOK + col);
                float2 m0 = *(const float2*)(mask_b + (size_t)q0 * NTOK + col);
                float2 m1 = *(const float2*)(mask_b + (size_t)(q0 + 8) * NTOK + col);
                float p0 = __expf(fmaf(s[mf][nf][0], scale, b0.x + m0.x));
                float p1 = __expf(fmaf(s[mf][nf][1], scale, b0.y + m0.y));
                float p2 = __expf(fmaf(s[mf][nf][2], scale, b1.x + m1.x));
                float p3 = __expf(fmaf(s[mf][nf][3], scale, b1.y + m1.y));
                Lp[mf][0] += p0 + p1;
                Lp[mf][1] += p2 + p3;
                int pr = mf * 16 + lr;
                *(float2*)&psh[pr * PPAD + nf * 8 + 2 * lc] =
                    make_float2(tf32_rn(p0), tf32_rn(p1));
                *(float2*)&psh[(pr + 8) * PPAD + nf * 8 + 2 * lc] =
                    make_float2(tf32_rn(p2), tf32_rn(p3));
            }
        }
        __syncwarp();

        // O += P V (k = 32 keys of this chunk)
        #pragma unroll
        for (int ks = 0; ks < 4; ks++) {
            uint32_t ap[2][4];
            #pragma unroll
            for (int mf = 0; mf < 2; mf++) {
                int rb = mf * 16 + lr;
                ap[mf][0] = __float_as_uint(psh[rb * PPAD + 8 * ks + lc]);
                ap[mf][1] = __float_as_uint(psh[(rb + 8) * PPAD + 8 * ks + lc]);
                ap[mf][2] = __float_as_uint(psh[rb * PPAD + 8 * ks + lc + 4]);
                ap[mf][3] = __float_as_uint(psh[(rb + 8) * PPAD + 8 * ks + lc + 4]);
            }
            uint32_t bv[4][2];
            int kk = kb + 8 * ks;
            #pragma unroll
            for (int nf = 0; nf < 4; nf++) {
                bv[nf][0] = __float_as_uint(vsh[(kk + lc) * VPAD + nf * 8 + lr]);
                bv[nf][1] = __float_as_uint(vsh[(kk + lc + 4) * VPAD + nf * 8 + lr]);
            }
            #pragma unroll
            for (int mf = 0; mf < 2; mf++)
                #pragma unroll
                for (int nf = 0; nf < 4; nf++)
                    mma_tf32_16x8x8(o[mf][nf], ap[mf], bv[nf]);
        }
        __syncwarp();
    }

    // L quad-reduce + normalized output (tf32 RNA for proj GEMM)
    #pragma unroll
    for (int mf = 0; mf < 2; mf++) {
        float L0 = Lp[mf][0], L1 = Lp[mf][1];
        L0 += __shfl_xor_sync(0xffffffffu, L0, 1);
        L0 += __shfl_xor_sync(0xffffffffu, L0, 2);
        L1 += __shfl_xor_sync(0xffffffffu, L1, 1);
        L1 += __shfl_xor_sync(0xffffffffu, L1, 2);
        float i0 = 1.f / L0, i1 = 1.f / L1;
        int q0 = wid * 32 + mf * 16 + lr;
        float* or0 = g_attn_out + ((size_t)b * NTOK + q0) * CDIM + h * HDIM;
        float* or1 = or0 + (size_t)8 * CDIM;
        #pragma unroll
        for (int nf = 0; nf < 4; nf++) {
            int d = nf * 8 + 2 * lc;
            *(float2*)(or0 + d) = make_float2(tf32_rn(o[mf][nf][0] * i0),
                                              tf32_rn(o[mf][nf][1] * i0));
            *(float2*)(or1 + d) = make_float2(tf32_rn(o[mf][nf][2] * i1),
                                              tf32_rn(o[mf][nf][3] * i1));
        }
    }
}

// ---------------------------------------------------------------------------
// Launch
// ---------------------------------------------------------------------------
extern "C" void kernel_launch(void* const* d_in, const int* in_sizes, int n_in,
                              void* d_out, int out_size) {
    const float* x          = (const float*)d_in[0];
    const float* mask       = (const float*)d_in[1];
    const float* qkv_w      = (const float*)d_in[2];
    const float* qkv_b      = (const float*)d_in[3];
    const float* proj_w     = (const float*)d_in[4];
    const float* proj_b     = (const float*)d_in[5];
    const float* rp_table   = (const float*)d_in[6];
    const int*   rp_index   = (const int*)d_in[7];
    float* out = (float*)d_out;

    void *p_qkv, *p_attn, *p_xr, *p_wq, *p_wp;
    cudaGetSymbolAddress(&p_qkv, g_qkv);
    cudaGetSymbolAddress(&p_attn, g_attn_out);
    cudaGetSymbolAddress(&p_xr, g_xr);
    cudaGetSymbolAddress(&p_wq, g_wq);
    cudaGetSymbolAddress(&p_wp, g_wp);
    float* qkv = (float*)p_qkv;
    float* attn_out = (float*)p_attn;
    float* xr = (float*)p_xr;
    float* wq = (float*)p_wq;
    float* wp = (float*)p_wp;

    const int gemm_smem = 4 * TILE_F * sizeof(float);
    cudaFuncSetAttribute(gemm_tf32,
                         cudaFuncAttributeMaxDynamicSharedMemorySize, gemm_smem);
    cudaFuncSetAttribute(attn_mma,
                         cudaFuncAttributeMaxDynamicSharedMemorySize, ATTN_SMEM);

    // 1) bias gather + tf32 rounding of GEMM inputs
    bias_gather_kernel<<<(NTOK * NTOK + 255) / 256, 256>>>(rp_table, rp_index);
    {
        int n4 = B_TOT * NTOK * CDIM / 4;
        round_tf32_kernel<<<(n4 + 255) / 256, 256>>>((const float4*)x, (float4*)xr, n4);
    }
    {
        int n4 = 3 * CDIM * CDIM / 4;
        round_tf32_kernel<<<(n4 + 255) / 256, 256>>>((const float4*)qkv_w, (float4*)wq, n4);
    }
    {
        int n4 = CDIM * CDIM / 4;
        round_tf32_kernel<<<(n4 + 255) / 256, 256>>>((const float4*)proj_w, (float4*)wp, n4);
    }

    // 2) qkv GEMM (rounded output -> exact tf32 inputs for attention MMAs)
    {
        int M = B_TOT * NTOK, N = 3 * CDIM, K = CDIM;
        dim3 grid(N / 128, M / 128);
        gemm_tf32<<<grid, 256, gemm_smem>>>(xr, wq, qkv_b, qkv, N, K, 1);
    }

    // 3) fused attention (tensor cores)
    attn_mma<<<B_TOT * HEADS, 256, ATTN_SMEM>>>(mask);

    // 4) proj GEMM
    {
        int M = B_TOT * NTOK, N = CDIM, K = CDIM;
        dim3 grid(N / 128, M / 128);
        gemm_tf32<<<grid, 256, gemm_smem>>>(attn_out, wp, proj_b, out, N, K, 0);
    }
}